// round 6
// baseline (speedup 1.0000x reference)
#include <cuda_runtime.h>

#define HH 1024
#define WW 1024
#define CC 8
#define NN 2
#define TH 32
#define TW 64
#define SROWS 64                 // TH + 32
#define SCOLS 96                 // TW + 32
#define SCH (SROWS*SCOLS)
#define NTHR 256

// ---- device-global scratch / accumulators ----
__device__ __align__(16) float g_scratch[NN*HH*WW];
__device__ unsigned int g_minbits;
__device__ unsigned int g_maxbits;
__device__ double g_sum;
__device__ unsigned long long g_cnt;

__global__ void init_k() {
    g_minbits = 0x7F800000u;
    g_maxbits = 0u;
    g_sum = 0.0;
    g_cnt = 0ull;
}

// Pass 1: gray diff + global min/max
__global__ void __launch_bounds__(256) mask_k(const float* __restrict__ mso,
                                              const float* __restrict__ pan) {
    int t = blockIdx.x * 256 + threadIdx.x;
    int p = t << 2;
    int n = p >> 20;
    int hw = p & 0xFFFFF;

    float4 acc = make_float4(0.f, 0.f, 0.f, 0.f);
#pragma unroll
    for (int c = 0; c < CC; c++) {
        float4 v = *(const float4*)&mso[((size_t)(n * CC + c) << 20) + hw];
        acc.x += v.x; acc.y += v.y; acc.z += v.z; acc.w += v.w;
    }
    float4 pv = *(const float4*)&pan[((size_t)n << 20) + hw];
    float4 g;
    g.x = fabsf(acc.x * 0.125f - pv.x);
    g.y = fabsf(acc.y * 0.125f - pv.y);
    g.z = fabsf(acc.z * 0.125f - pv.z);
    g.w = fabsf(acc.w * 0.125f - pv.w);
    *(float4*)&g_scratch[p] = g;

    float lmin = fminf(fminf(g.x, g.y), fminf(g.z, g.w));
    float lmax = fmaxf(fmaxf(g.x, g.y), fmaxf(g.z, g.w));
#pragma unroll
    for (int o = 16; o; o >>= 1) {
        lmin = fminf(lmin, __shfl_xor_sync(0xffffffffu, lmin, o));
        lmax = fmaxf(lmax, __shfl_xor_sync(0xffffffffu, lmax, o));
    }
    __shared__ float smn[8], smx[8];
    int lane = threadIdx.x & 31, wid = threadIdx.x >> 5;
    if (!lane) { smn[wid] = lmin; smx[wid] = lmax; }
    __syncthreads();
    if (threadIdx.x == 0) {
        float mn = smn[0], mx = smx[0];
#pragma unroll
        for (int i = 1; i < 8; i++) { mn = fminf(mn, smn[i]); mx = fmaxf(mx, smx[i]); }
        atomicMin(&g_minbits, __float_as_uint(mn));
        atomicMax(&g_maxbits, __float_as_uint(mx));
    }
}

// One sliding-window step: row segment (r0 + 4k) feeds px0 @ di=k and px1 @ di=k-1.
template<bool DO0, bool DO1>
__device__ __forceinline__ void sad_step(const float* __restrict__ sT, int rb,
                                         const float4* __restrict__ m0r,
                                         const float4* __restrict__ m1r,
                                         float* __restrict__ minv0,
                                         float* __restrict__ minv1) {
    float part0[36], part1[36];
    if (DO0) {
#pragma unroll
        for (int i = 0; i < 36; i++) part0[i] = 0.f;
    }
    if (DO1) {
#pragma unroll
        for (int i = 0; i < 36; i++) part1[i] = 0.f;
    }
#pragma unroll
    for (int c = 0; c < CC; c++) {
        const float* p = sT + c * SCH + rb;
        const float4 m0 = m0r[c];
        const float4 m1 = m1r[c];
#pragma unroll
        for (int dj = 0; dj < 9; dj++) {
            float4 tv = *(const float4*)(p + (dj << 2));
            if (DO0) {
                part0[dj * 4 + 0] += fabsf(m0.x - tv.x);
                part0[dj * 4 + 1] += fabsf(m0.y - tv.y);
                part0[dj * 4 + 2] += fabsf(m0.z - tv.z);
                part0[dj * 4 + 3] += fabsf(m0.w - tv.w);
            }
            if (DO1) {
                part1[dj * 4 + 0] += fabsf(m1.x - tv.x);
                part1[dj * 4 + 1] += fabsf(m1.y - tv.y);
                part1[dj * 4 + 2] += fabsf(m1.z - tv.z);
                part1[dj * 4 + 3] += fabsf(m1.w - tv.w);
            }
        }
    }
    if (DO0) {
#pragma unroll
        for (int dj = 0; dj < 9; dj++)
#pragma unroll
            for (int i = 0; i < 4; i++)
                minv0[i] = fminf(minv0[i], part0[dj * 4 + i]);
    }
    if (DO1) {
#pragma unroll
        for (int dj = 0; dj < 9; dj++)
#pragma unroll
            for (int i = 0; i < 4; i++)
                minv1[i] = fminf(minv1[i], part1[dj * 4 + i]);
    }
}

// Pass 2: min-shift SAD, 256 threads, 2 rows x 4 px per thread, sliding di window
__global__ void __launch_bounds__(NTHR, 1) main_k(const float* __restrict__ ms,
                                                  const float* __restrict__ tgt) {
    extern __shared__ float sT[];   // [CC][SROWS][SCOLS]

    const int n  = blockIdx.z;
    const int h0 = blockIdx.y * TH;
    const int w0 = blockIdx.x * TW;
    const int tx = threadIdx.x;      // 0..15 -> 4 px along w
    const int ty = threadIdx.y;      // 0..15 -> rows r0 and r0+4
    const int tid = ty * 16 + tx;

    // ---- load target tile (reflect pad), vectorized ----
    const int CPL4 = SCOLS / 4;                // 24 float4 per row
    const int NV4  = CC * SROWS * CPL4;        // 12288 = 48 * 256
#pragma unroll 4
    for (int it = 0; it < NV4 / NTHR; it++) {
        int e4  = it * NTHR + tid;
        int c   = e4 / (SROWS * CPL4);
        int rem = e4 - c * (SROWS * CPL4);
        int r   = rem / CPL4;
        int q   = rem - r * CPL4;
        int gr = h0 + r - 16;
        gr = gr < 0 ? -gr : (gr >= HH ? 2 * HH - 2 - gr : gr);
        const float* src = tgt + (((size_t)n * CC + c) * HH + gr) * WW;
        int gcb = w0 + q * 4 - 16;
        float4 v;
        if (gcb >= 0 && gcb + 4 <= WW) {
            v = *(const float4*)(src + gcb);
        } else {
            int g0 = gcb, g1 = gcb + 1, g2 = gcb + 2, g3 = gcb + 3;
            g0 = g0 < 0 ? -g0 : (g0 >= WW ? 2 * WW - 2 - g0 : g0);
            g1 = g1 < 0 ? -g1 : (g1 >= WW ? 2 * WW - 2 - g1 : g1);
            g2 = g2 < 0 ? -g2 : (g2 >= WW ? 2 * WW - 2 - g2 : g2);
            g3 = g3 < 0 ? -g3 : (g3 >= WW ? 2 * WW - 2 - g3 : g3);
            v = make_float4(src[g0], src[g1], src[g2], src[g3]);
        }
        *(float4*)&sT[c * SCH + r * SCOLS + q * 4] = v;
    }
    __syncthreads();

    // rows owned by this thread: r0 and r0+4 (disjoint cover of 0..31)
    const int r0    = (ty & 3) + ((ty >> 2) << 3);
    const int r1    = r0 + 4;
    const int wbase = w0 + (tx << 2);

    // ms pixels: 8 channels x 4 px, two rows
    float4 m0r[CC], m1r[CC];
#pragma unroll
    for (int c = 0; c < CC; c++) {
        const float* base = &ms[(((size_t)n * CC + c) * HH + h0) * WW + wbase];
        m0r[c] = *(const float4*)(base + (size_t)r0 * WW);
        m1r[c] = *(const float4*)(base + (size_t)r1 * WW);
    }

    float minv0[4] = {3.4e38f, 3.4e38f, 3.4e38f, 3.4e38f};
    float minv1[4] = {3.4e38f, 3.4e38f, 3.4e38f, 3.4e38f};

    const int rbase = r0 * SCOLS + (tx << 2);

    sad_step<true, false>(sT, rbase, m0r, m1r, minv0, minv1);            // k = 0
#pragma unroll 1
    for (int k = 1; k < 9; k++)
        sad_step<true, true>(sT, rbase + k * 4 * SCOLS, m0r, m1r, minv0, minv1);
    sad_step<false, true>(sT, rbase + 9 * 4 * SCOLS, m0r, m1r, minv0, minv1);  // k = 9

    // ---- mask + reduction ----
    const float mn  = __uint_as_float(g_minbits);
    const float mx  = __uint_as_float(g_maxbits);
    const float thr = mn + (mx - mn) * (10.0f / 255.0f);

    const float* gbase = &g_scratch[((size_t)n << 20) + (size_t)(h0) * WW + wbase];
    float4 ga = *(const float4*)(gbase + (size_t)r0 * WW);
    float4 gb = *(const float4*)(gbase + (size_t)r1 * WW);

    float lsum = 0.f;
    int   lcnt = 0;
    if (ga.x > thr) { lsum += minv0[0]; lcnt++; }
    if (ga.y > thr) { lsum += minv0[1]; lcnt++; }
    if (ga.z > thr) { lsum += minv0[2]; lcnt++; }
    if (ga.w > thr) { lsum += minv0[3]; lcnt++; }
    if (gb.x > thr) { lsum += minv1[0]; lcnt++; }
    if (gb.y > thr) { lsum += minv1[1]; lcnt++; }
    if (gb.z > thr) { lsum += minv1[2]; lcnt++; }
    if (gb.w > thr) { lsum += minv1[3]; lcnt++; }

#pragma unroll
    for (int o = 16; o; o >>= 1) {
        lsum += __shfl_xor_sync(0xffffffffu, lsum, o);
        lcnt += __shfl_xor_sync(0xffffffffu, lcnt, o);
    }
    __shared__ float wsum[8];
    __shared__ int   wcnt[8];
    int lane = tid & 31, wid = tid >> 5;
    if (!lane) { wsum[wid] = lsum; wcnt[wid] = lcnt; }
    __syncthreads();
    if (tid == 0) {
        double bs = 0.0; long long bc = 0;
#pragma unroll
        for (int i = 0; i < 8; i++) { bs += (double)wsum[i]; bc += wcnt[i]; }
        atomicAdd(&g_sum, bs);
        atomicAdd(&g_cnt, (unsigned long long)bc);
    }
}

__global__ void fin_k(float* out) {
    unsigned long long c = g_cnt;
    out[0] = (c > 0ull) ? (float)(g_sum / (double)c) : 0.0f;
}

extern "C" void kernel_launch(void* const* d_in, const int* in_sizes, int n_in,
                              void* d_out, int out_size) {
    const float* ms  = (const float*)d_in[0];
    const float* tgt = (const float*)d_in[1];
    const float* mso = (const float*)d_in[2];
    const float* pan = (const float*)d_in[3];
    float* out = (float*)d_out;

    const int smem = CC * SCH * (int)sizeof(float);   // 196608 B
    cudaFuncSetAttribute(main_k, cudaFuncAttributeMaxDynamicSharedMemorySize, smem);

    init_k<<<1, 1>>>();
    mask_k<<<(NN * HH * WW) / 4 / 256, 256>>>(mso, pan);
    dim3 grid(WW / TW, HH / TH, NN), blk(16, 16);
    main_k<<<grid, blk, smem>>>(ms, tgt);
    fin_k<<<1, 1>>>(out);
}

// round 7
// speedup vs baseline: 1.2637x; 1.2637x over previous
#include <cuda_runtime.h>

#define HH 1024
#define WW 1024
#define CC 8
#define NN 2
#define TH 32
#define TW 64
#define SROWS 64                 // TH + 32
#define SCOLS 96                 // TW + 32
#define SCH (SROWS*SCOLS)
#define NTHR 512

// ---- device-global scratch / accumulators ----
__device__ __align__(16) float g_scratch[NN*HH*WW];
__device__ unsigned int g_minbits;
__device__ unsigned int g_maxbits;
__device__ double g_sum;
__device__ unsigned long long g_cnt;

__global__ void init_k() {
    g_minbits = 0x7F800000u;
    g_maxbits = 0u;
    g_sum = 0.0;
    g_cnt = 0ull;
}

// Pass 1: gray diff + global min/max
__global__ void __launch_bounds__(256) mask_k(const float* __restrict__ mso,
                                              const float* __restrict__ pan) {
    int t = blockIdx.x * 256 + threadIdx.x;
    int p = t << 2;
    int n = p >> 20;
    int hw = p & 0xFFFFF;

    float4 acc = make_float4(0.f, 0.f, 0.f, 0.f);
#pragma unroll
    for (int c = 0; c < CC; c++) {
        float4 v = *(const float4*)&mso[((size_t)(n * CC + c) << 20) + hw];
        acc.x += v.x; acc.y += v.y; acc.z += v.z; acc.w += v.w;
    }
    float4 pv = *(const float4*)&pan[((size_t)n << 20) + hw];
    float4 g;
    g.x = fabsf(acc.x * 0.125f - pv.x);
    g.y = fabsf(acc.y * 0.125f - pv.y);
    g.z = fabsf(acc.z * 0.125f - pv.z);
    g.w = fabsf(acc.w * 0.125f - pv.w);
    *(float4*)&g_scratch[p] = g;

    float lmin = fminf(fminf(g.x, g.y), fminf(g.z, g.w));
    float lmax = fmaxf(fmaxf(g.x, g.y), fmaxf(g.z, g.w));
#pragma unroll
    for (int o = 16; o; o >>= 1) {
        lmin = fminf(lmin, __shfl_xor_sync(0xffffffffu, lmin, o));
        lmax = fmaxf(lmax, __shfl_xor_sync(0xffffffffu, lmax, o));
    }
    __shared__ float smn[8], smx[8];
    int lane = threadIdx.x & 31, wid = threadIdx.x >> 5;
    if (!lane) { smn[wid] = lmin; smx[wid] = lmax; }
    __syncthreads();
    if (threadIdx.x == 0) {
        float mn = smn[0], mx = smx[0];
#pragma unroll
        for (int i = 1; i < 8; i++) { mn = fminf(mn, smn[i]); mx = fmaxf(mx, smx[i]); }
        atomicMin(&g_minbits, __float_as_uint(mn));
        atomicMax(&g_maxbits, __float_as_uint(mx));
    }
}

// One sliding-window step: target row (r0 + 4k) feeds px-row0 @ di=k and px-row1 @ di=k-1.
template<bool DO0, bool DO1>
__device__ __forceinline__ void sad_step(const float* __restrict__ sT, int rb,
                                         const float2* __restrict__ m0r,
                                         const float2* __restrict__ m1r,
                                         float* __restrict__ minv0,
                                         float* __restrict__ minv1) {
    float part0[18], part1[18];
    if (DO0) {
#pragma unroll
        for (int i = 0; i < 18; i++) part0[i] = 0.f;
    }
    if (DO1) {
#pragma unroll
        for (int i = 0; i < 18; i++) part1[i] = 0.f;
    }
#pragma unroll
    for (int c = 0; c < CC; c++) {
        const float* p = sT + c * SCH + rb;
        const float2 m0 = m0r[c];
        const float2 m1 = m1r[c];
#pragma unroll
        for (int dj = 0; dj < 9; dj++) {
            float2 tv = *(const float2*)(p + (dj << 2));
            if (DO0) {
                part0[dj * 2 + 0] += fabsf(m0.x - tv.x);
                part0[dj * 2 + 1] += fabsf(m0.y - tv.y);
            }
            if (DO1) {
                part1[dj * 2 + 0] += fabsf(m1.x - tv.x);
                part1[dj * 2 + 1] += fabsf(m1.y - tv.y);
            }
        }
    }
    if (DO0) {
#pragma unroll
        for (int dj = 0; dj < 9; dj++) {
            minv0[0] = fminf(minv0[0], part0[dj * 2 + 0]);
            minv0[1] = fminf(minv0[1], part0[dj * 2 + 1]);
        }
    }
    if (DO1) {
#pragma unroll
        for (int dj = 0; dj < 9; dj++) {
            minv1[0] = fminf(minv1[0], part1[dj * 2 + 0]);
            minv1[1] = fminf(minv1[1], part1[dj * 2 + 1]);
        }
    }
}

// Pass 2: min-shift SAD, 512 threads, 2 rows x 2 px per thread, sliding di window
__global__ void __launch_bounds__(NTHR, 1) main_k(const float* __restrict__ ms,
                                                  const float* __restrict__ tgt) {
    extern __shared__ float sT[];   // [CC][SROWS][SCOLS]

    const int n  = blockIdx.z;
    const int h0 = blockIdx.y * TH;
    const int w0 = blockIdx.x * TW;
    const int tx = threadIdx.x;      // 0..31 -> 2 px along w
    const int ty = threadIdx.y;      // 0..15 -> rows r0 and r0+4
    const int tid = ty * 32 + tx;

    // ---- load target tile (reflect pad), vectorized ----
    const int CPL4 = SCOLS / 4;                // 24 float4 per row
    const int NV4  = CC * SROWS * CPL4;        // 12288 = 24 * 512
#pragma unroll 4
    for (int it = 0; it < NV4 / NTHR; it++) {
        int e4  = it * NTHR + tid;
        int c   = e4 / (SROWS * CPL4);
        int rem = e4 - c * (SROWS * CPL4);
        int r   = rem / CPL4;
        int q   = rem - r * CPL4;
        int gr = h0 + r - 16;
        gr = gr < 0 ? -gr : (gr >= HH ? 2 * HH - 2 - gr : gr);
        const float* src = tgt + (((size_t)n * CC + c) * HH + gr) * WW;
        int gcb = w0 + q * 4 - 16;
        float4 v;
        if (gcb >= 0 && gcb + 4 <= WW) {
            v = *(const float4*)(src + gcb);
        } else {
            int g0 = gcb, g1 = gcb + 1, g2 = gcb + 2, g3 = gcb + 3;
            g0 = g0 < 0 ? -g0 : (g0 >= WW ? 2 * WW - 2 - g0 : g0);
            g1 = g1 < 0 ? -g1 : (g1 >= WW ? 2 * WW - 2 - g1 : g1);
            g2 = g2 < 0 ? -g2 : (g2 >= WW ? 2 * WW - 2 - g2 : g2);
            g3 = g3 < 0 ? -g3 : (g3 >= WW ? 2 * WW - 2 - g3 : g3);
            v = make_float4(src[g0], src[g1], src[g2], src[g3]);
        }
        *(float4*)&sT[c * SCH + r * SCOLS + q * 4] = v;
    }
    __syncthreads();

    // rows owned by this thread: r0 and r0+4 (disjoint cover of 0..31)
    const int r0    = (ty & 3) + ((ty >> 2) << 3);
    const int r1    = r0 + 4;
    const int wbase = w0 + (tx << 1);

    // ms pixels: 8 channels x 2 px, two rows
    float2 m0r[CC], m1r[CC];
#pragma unroll
    for (int c = 0; c < CC; c++) {
        const float* base = &ms[(((size_t)n * CC + c) * HH + h0) * WW + wbase];
        m0r[c] = *(const float2*)(base + (size_t)r0 * WW);
        m1r[c] = *(const float2*)(base + (size_t)r1 * WW);
    }

    float minv0[2] = {3.4e38f, 3.4e38f};
    float minv1[2] = {3.4e38f, 3.4e38f};

    const int rbase = r0 * SCOLS + (tx << 1);

    sad_step<true, false>(sT, rbase, m0r, m1r, minv0, minv1);            // k = 0
#pragma unroll 1
    for (int k = 1; k < 9; k++)
        sad_step<true, true>(sT, rbase + k * 4 * SCOLS, m0r, m1r, minv0, minv1);
    sad_step<false, true>(sT, rbase + 9 * 4 * SCOLS, m0r, m1r, minv0, minv1);  // k = 9

    // ---- mask + reduction ----
    const float mn  = __uint_as_float(g_minbits);
    const float mx  = __uint_as_float(g_maxbits);
    const float thr = mn + (mx - mn) * (10.0f / 255.0f);

    const float* gbase = &g_scratch[((size_t)n << 20) + (size_t)h0 * WW + wbase];
    float2 ga = *(const float2*)(gbase + (size_t)r0 * WW);
    float2 gb = *(const float2*)(gbase + (size_t)r1 * WW);

    float lsum = 0.f;
    int   lcnt = 0;
    if (ga.x > thr) { lsum += minv0[0]; lcnt++; }
    if (ga.y > thr) { lsum += minv0[1]; lcnt++; }
    if (gb.x > thr) { lsum += minv1[0]; lcnt++; }
    if (gb.y > thr) { lsum += minv1[1]; lcnt++; }

#pragma unroll
    for (int o = 16; o; o >>= 1) {
        lsum += __shfl_xor_sync(0xffffffffu, lsum, o);
        lcnt += __shfl_xor_sync(0xffffffffu, lcnt, o);
    }
    __shared__ float wsum[16];
    __shared__ int   wcnt[16];
    int lane = tid & 31, wid = tid >> 5;
    if (!lane) { wsum[wid] = lsum; wcnt[wid] = lcnt; }
    __syncthreads();
    if (tid == 0) {
        double bs = 0.0; long long bc = 0;
#pragma unroll
        for (int i = 0; i < 16; i++) { bs += (double)wsum[i]; bc += wcnt[i]; }
        atomicAdd(&g_sum, bs);
        atomicAdd(&g_cnt, (unsigned long long)bc);
    }
}

__global__ void fin_k(float* out) {
    unsigned long long c = g_cnt;
    out[0] = (c > 0ull) ? (float)(g_sum / (double)c) : 0.0f;
}

extern "C" void kernel_launch(void* const* d_in, const int* in_sizes, int n_in,
                              void* d_out, int out_size) {
    const float* ms  = (const float*)d_in[0];
    const float* tgt = (const float*)d_in[1];
    const float* mso = (const float*)d_in[2];
    const float* pan = (const float*)d_in[3];
    float* out = (float*)d_out;

    const int smem = CC * SCH * (int)sizeof(float);   // 196608 B
    cudaFuncSetAttribute(main_k, cudaFuncAttributeMaxDynamicSharedMemorySize, smem);

    init_k<<<1, 1>>>();
    mask_k<<<(NN * HH * WW) / 4 / 256, 256>>>(mso, pan);
    dim3 grid(WW / TW, HH / TH, NN), blk(32, 16);
    main_k<<<grid, blk, smem>>>(ms, tgt);
    fin_k<<<1, 1>>>(out);
}